// round 10
// baseline (speedup 1.0000x reference)
#include <cuda_runtime.h>
#include <cuda_bf16.h>
#include <cstdint>

// AddRadiusEdgeIndex: N=8192 points in [0,10]^3, r=1.
// out[0 : N*N)     = masked_dist2 (float32)
// out[N*N : 2*N*N) = edge_mask as 0.0/1.0 float32
//
// R8 champion (64 x 1024 tile, 256 thr, 4 cols/thr, vectorized pj loads,
// STG.128 streaming) squeezed to a 32-reg budget via __launch_bounds__(256,8):
// 8 CTAs/SM -> all 1024 CTAs resident in ONE wave (1184 capacity), zero tail,
// 64 warps/SM of store MLP. Arithmetic bit-identical to the reference formula.

#define NPTS  8192
#define ITILE 64
#define JTILE 1024   // 256 threads * 4 cols
#define TPB   256

#define MASK_OFF ((size_t)NPTS * NPTS)

__global__ void __launch_bounds__(TPB, 8) radius_kernel(const float* __restrict__ pos,
                                                        float* __restrict__ out) {
    __shared__ float4 s_pi[ITILE];

    const int i0 = blockIdx.y * ITILE;
    const int j0 = blockIdx.x * JTILE + threadIdx.x * 4;

    // 4 consecutive points = 12 contiguous floats, 16B-aligned (48*tid offset).
    const float4* p4 = reinterpret_cast<const float4*>(pos + 3 * (size_t)j0);
    const float4 va = p4[0];
    const float4 vb = p4[1];
    const float4 vc = p4[2];

    float4 pj[4];
    {
        const float px[4] = {va.x, va.w, vb.z, vc.y};
        const float py[4] = {va.y, vb.x, vb.w, vc.z};
        const float pz[4] = {va.z, vb.y, vc.x, vc.w};
#pragma unroll
        for (int k = 0; k < 4; k++) {
            float s = __fmul_rn(px[k], px[k]);
            s = __fmaf_rn(py[k], py[k], s);
            s = __fmaf_rn(pz[k], pz[k], s);
            pj[k] = make_float4(px[k], py[k], pz[k], s);
        }
    }

    // Row tile into smem: threads 0..63 each build one pi (once per block).
    if (threadIdx.x < ITILE) {
        const int i = i0 + threadIdx.x;
        const float x = pos[3 * i + 0];
        const float y = pos[3 * i + 1];
        const float z = pos[3 * i + 2];
        float s = __fmul_rn(x, x);
        s = __fmaf_rn(y, y, s);
        s = __fmaf_rn(z, z, s);
        s_pi[threadIdx.x] = make_float4(x, y, z, s);
    }
    __syncthreads();

    // Single running pointer; mask half addressed by constant offset at use.
    float* od = out + (size_t)i0 * NPTS + j0;

#pragma unroll 4
    for (int r = 0; r < ITILE; r++) {
        const float4 pi = s_pi[r];  // broadcast LDS, conflict-free

        float d[4], m[4];
#pragma unroll
        for (int k = 0; k < 4; k++) {
            float dot = __fmul_rn(pi.x, pj[k].x);
            dot = __fmaf_rn(pi.y, pj[k].y, dot);
            dot = __fmaf_rn(pi.z, pj[k].z, dot);
            // (sq_i + sq_j) - 2*dot : exact rounding order, no fma contraction
            float dd = __fsub_rn(__fadd_rn(pi.w, pj[k].w), __fmul_rn(2.0f, dot));
            dd = fmaxf(dd, 0.0f);
            const bool e = (dd <= 1.0f);
            d[k] = e ? dd : 0.0f;
            m[k] = e ? 1.0f : 0.0f;
        }

        __stcs(reinterpret_cast<float4*>(od), make_float4(d[0], d[1], d[2], d[3]));
        __stcs(reinterpret_cast<float4*>(od + MASK_OFF), make_float4(m[0], m[1], m[2], m[3]));
        od += NPTS;
    }
}

extern "C" void kernel_launch(void* const* d_in, const int* in_sizes, int n_in,
                              void* d_out, int out_size) {
    const float* pos = (const float*)d_in[0];
    float* out = (float*)d_out;

    dim3 grid(NPTS / JTILE, NPTS / ITILE);  // (8, 128) = 1024 CTAs, one wave @ 8/SM
    radius_kernel<<<grid, TPB>>>(pos, out);
}

// round 12
// speedup vs baseline: 1.0674x; 1.0674x over previous
#include <cuda_runtime.h>
#include <cuda_bf16.h>
#include <cstdint>

// AddRadiusEdgeIndex: N=8192 points in [0,10]^3, r=1.  FINAL (locked champion)
// out[0 : N*N)     = masked_dist2 (float32)
// out[N*N : 2*N*N) = edge_mask as 0.0/1.0 float32
//
// 64 x 1024 tile, 256 threads, 4 cols/thread, regs 40, 6 CTAs/SM.
// pj loads vectorized (3x LDG.128/thread); pi rows broadcast from smem.
// Stores: 2x STG.128 streaming per thread per row; 537 MB mandatory writes.
// Measured at ~6.0 TB/s DRAM = the B300 pure-write ceiling (all structural
// perturbations — wider stores, more threads, other tile shapes, forced
// occupancy — regressed 4-36%). Arithmetic matches the reference rounding
// order exactly (rel_err 1.397e-5, boundary-flip-free).

#define NPTS  8192
#define ITILE 64
#define JTILE 1024   // 256 threads * 4 cols
#define TPB   256

__global__ void __launch_bounds__(TPB) radius_kernel(const float* __restrict__ pos,
                                                     float* __restrict__ out) {
    __shared__ float4 s_pi[ITILE];

    const int i0 = blockIdx.y * ITILE;
    const int j0 = blockIdx.x * JTILE + threadIdx.x * 4;

    // 4 consecutive points = 12 contiguous floats, 16B-aligned (48*tid offset).
    const float4* p4 = reinterpret_cast<const float4*>(pos + 3 * (size_t)j0);
    const float4 va = p4[0];
    const float4 vb = p4[1];
    const float4 vc = p4[2];

    float4 pj[4];
    {
        const float px[4] = {va.x, va.w, vb.z, vc.y};
        const float py[4] = {va.y, vb.x, vb.w, vc.z};
        const float pz[4] = {va.z, vb.y, vc.x, vc.w};
#pragma unroll
        for (int k = 0; k < 4; k++) {
            float s = __fmul_rn(px[k], px[k]);
            s = __fmaf_rn(py[k], py[k], s);
            s = __fmaf_rn(pz[k], pz[k], s);
            pj[k] = make_float4(px[k], py[k], pz[k], s);
        }
    }

    // Row tile into smem: threads 0..63 each build one pi (once per block).
    if (threadIdx.x < ITILE) {
        const int i = i0 + threadIdx.x;
        const float x = pos[3 * i + 0];
        const float y = pos[3 * i + 1];
        const float z = pos[3 * i + 2];
        float s = __fmul_rn(x, x);
        s = __fmaf_rn(y, y, s);
        s = __fmaf_rn(z, z, s);
        s_pi[threadIdx.x] = make_float4(x, y, z, s);
    }
    __syncthreads();

    float* od = out + (size_t)i0 * NPTS + j0;
    float* om = od + (size_t)NPTS * NPTS;

#pragma unroll 4
    for (int r = 0; r < ITILE; r++) {
        const float4 pi = s_pi[r];  // broadcast LDS, conflict-free

        float d[4], m[4];
#pragma unroll
        for (int k = 0; k < 4; k++) {
            float dot = __fmul_rn(pi.x, pj[k].x);
            dot = __fmaf_rn(pi.y, pj[k].y, dot);
            dot = __fmaf_rn(pi.z, pj[k].z, dot);
            // (sq_i + sq_j) - 2*dot : exact rounding order, no fma contraction
            float dd = __fsub_rn(__fadd_rn(pi.w, pj[k].w), __fmul_rn(2.0f, dot));
            dd = fmaxf(dd, 0.0f);
            const bool e = (dd <= 1.0f);
            d[k] = e ? dd : 0.0f;
            m[k] = e ? 1.0f : 0.0f;
        }

        __stcs(reinterpret_cast<float4*>(od), make_float4(d[0], d[1], d[2], d[3]));
        __stcs(reinterpret_cast<float4*>(om), make_float4(m[0], m[1], m[2], m[3]));
        od += NPTS;
        om += NPTS;
    }
}

extern "C" void kernel_launch(void* const* d_in, const int* in_sizes, int n_in,
                              void* d_out, int out_size) {
    const float* pos = (const float*)d_in[0];
    float* out = (float*)d_out;

    dim3 grid(NPTS / JTILE, NPTS / ITILE);  // (8, 128) = 1024 CTAs
    radius_kernel<<<grid, TPB>>>(pos, out);
}

// round 13
// speedup vs baseline: 1.0695x; 1.0020x over previous
#include <cuda_runtime.h>
#include <cuda_bf16.h>
#include <cstdint>

// AddRadiusEdgeIndex: N=8192 points in [0,10]^3, r=1.
// out[0 : N*N)     = masked_dist2 (float32)
// out[N*N : 2*N*N) = edge_mask as 0.0/1.0 float32
//
// Champion config: 64 x 1024 tile, 256 threads, 4 cols/thread, regs 40.
// pj loads vectorized (3x LDG.128/thread); pi rows broadcast from smem.
// This round's single A/B: default write-back STG.128 instead of __stcs
// (last untested lever; everything else byte-identical to the 80.35us champ).

#define NPTS  8192
#define ITILE 64
#define JTILE 1024   // 256 threads * 4 cols
#define TPB   256

__global__ void __launch_bounds__(TPB) radius_kernel(const float* __restrict__ pos,
                                                     float* __restrict__ out) {
    __shared__ float4 s_pi[ITILE];

    const int i0 = blockIdx.y * ITILE;
    const int j0 = blockIdx.x * JTILE + threadIdx.x * 4;

    // 4 consecutive points = 12 contiguous floats, 16B-aligned (48*tid offset).
    const float4* p4 = reinterpret_cast<const float4*>(pos + 3 * (size_t)j0);
    const float4 va = p4[0];
    const float4 vb = p4[1];
    const float4 vc = p4[2];

    float4 pj[4];
    {
        const float px[4] = {va.x, va.w, vb.z, vc.y};
        const float py[4] = {va.y, vb.x, vb.w, vc.z};
        const float pz[4] = {va.z, vb.y, vc.x, vc.w};
#pragma unroll
        for (int k = 0; k < 4; k++) {
            float s = __fmul_rn(px[k], px[k]);
            s = __fmaf_rn(py[k], py[k], s);
            s = __fmaf_rn(pz[k], pz[k], s);
            pj[k] = make_float4(px[k], py[k], pz[k], s);
        }
    }

    // Row tile into smem: threads 0..63 each build one pi (once per block).
    if (threadIdx.x < ITILE) {
        const int i = i0 + threadIdx.x;
        const float x = pos[3 * i + 0];
        const float y = pos[3 * i + 1];
        const float z = pos[3 * i + 2];
        float s = __fmul_rn(x, x);
        s = __fmaf_rn(y, y, s);
        s = __fmaf_rn(z, z, s);
        s_pi[threadIdx.x] = make_float4(x, y, z, s);
    }
    __syncthreads();

    float* od = out + (size_t)i0 * NPTS + j0;
    float* om = od + (size_t)NPTS * NPTS;

#pragma unroll 4
    for (int r = 0; r < ITILE; r++) {
        const float4 pi = s_pi[r];  // broadcast LDS, conflict-free

        float d[4], m[4];
#pragma unroll
        for (int k = 0; k < 4; k++) {
            float dot = __fmul_rn(pi.x, pj[k].x);
            dot = __fmaf_rn(pi.y, pj[k].y, dot);
            dot = __fmaf_rn(pi.z, pj[k].z, dot);
            // (sq_i + sq_j) - 2*dot : exact rounding order, no fma contraction
            float dd = __fsub_rn(__fadd_rn(pi.w, pj[k].w), __fmul_rn(2.0f, dot));
            dd = fmaxf(dd, 0.0f);
            const bool e = (dd <= 1.0f);
            d[k] = e ? dd : 0.0f;
            m[k] = e ? 1.0f : 0.0f;
        }

        // Default write-back stores (A/B vs __stcs streaming).
        *reinterpret_cast<float4*>(od) = make_float4(d[0], d[1], d[2], d[3]);
        *reinterpret_cast<float4*>(om) = make_float4(m[0], m[1], m[2], m[3]);
        od += NPTS;
        om += NPTS;
    }
}

extern "C" void kernel_launch(void* const* d_in, const int* in_sizes, int n_in,
                              void* d_out, int out_size) {
    const float* pos = (const float*)d_in[0];
    float* out = (float*)d_out;

    dim3 grid(NPTS / JTILE, NPTS / ITILE);  // (8, 128) = 1024 CTAs
    radius_kernel<<<grid, TPB>>>(pos, out);
}

// round 15
// speedup vs baseline: 1.0789x; 1.0088x over previous
#include <cuda_runtime.h>
#include <cuda_bf16.h>
#include <cstdint>

// AddRadiusEdgeIndex: N=8192 points in [0,10]^3, r=1.  FINAL — locked champion.
// out[0 : N*N)     = masked_dist2 (float32)
// out[N*N : 2*N*N) = edge_mask as 0.0/1.0 float32
//
// 64 x 1024 tile, 256 threads, 4 cols/thread, regs 40, ~6 CTAs/SM.
// pj: 3x aligned LDG.128 per thread; pi: smem broadcast (64x reuse).
// Stores: 2x STG.128 streaming per thread per row; 537 MB mandatory writes
// at ~6.1-6.2 TB/s = B300 pure-write ceiling. All structural perturbations
// (wider stores, 512-thr, tile 128/32, forced occ-8, write-back policy)
// measured and regressed or neutral. Arithmetic reproduces the reference
// rounding order exactly: sq/dot fma chains + rn add/sub/mul for
// (sq_i + sq_j) - 2*dot, no re-contraction -> rel_err 1.397e-5 stable.

#define NPTS  8192
#define ITILE 64
#define JTILE 1024   // 256 threads * 4 cols
#define TPB   256

__global__ void __launch_bounds__(TPB) radius_kernel(const float* __restrict__ pos,
                                                     float* __restrict__ out) {
    __shared__ float4 s_pi[ITILE];

    const int i0 = blockIdx.y * ITILE;
    const int j0 = blockIdx.x * JTILE + threadIdx.x * 4;

    // 4 consecutive points = 12 contiguous floats, 16B-aligned (48*tid offset).
    const float4* p4 = reinterpret_cast<const float4*>(pos + 3 * (size_t)j0);
    const float4 va = p4[0];
    const float4 vb = p4[1];
    const float4 vc = p4[2];

    float4 pj[4];
    {
        const float px[4] = {va.x, va.w, vb.z, vc.y};
        const float py[4] = {va.y, vb.x, vb.w, vc.z};
        const float pz[4] = {va.z, vb.y, vc.x, vc.w};
#pragma unroll
        for (int k = 0; k < 4; k++) {
            float s = __fmul_rn(px[k], px[k]);
            s = __fmaf_rn(py[k], py[k], s);
            s = __fmaf_rn(pz[k], pz[k], s);
            pj[k] = make_float4(px[k], py[k], pz[k], s);
        }
    }

    // Row tile into smem: threads 0..63 each build one pi (once per block).
    if (threadIdx.x < ITILE) {
        const int i = i0 + threadIdx.x;
        const float x = pos[3 * i + 0];
        const float y = pos[3 * i + 1];
        const float z = pos[3 * i + 2];
        float s = __fmul_rn(x, x);
        s = __fmaf_rn(y, y, s);
        s = __fmaf_rn(z, z, s);
        s_pi[threadIdx.x] = make_float4(x, y, z, s);
    }
    __syncthreads();

    float* od = out + (size_t)i0 * NPTS + j0;
    float* om = od + (size_t)NPTS * NPTS;

#pragma unroll 4
    for (int r = 0; r < ITILE; r++) {
        const float4 pi = s_pi[r];  // broadcast LDS, conflict-free

        float d[4], m[4];
#pragma unroll
        for (int k = 0; k < 4; k++) {
            float dot = __fmul_rn(pi.x, pj[k].x);
            dot = __fmaf_rn(pi.y, pj[k].y, dot);
            dot = __fmaf_rn(pi.z, pj[k].z, dot);
            // (sq_i + sq_j) - 2*dot : exact rounding order, no fma contraction
            float dd = __fsub_rn(__fadd_rn(pi.w, pj[k].w), __fmul_rn(2.0f, dot));
            dd = fmaxf(dd, 0.0f);
            const bool e = (dd <= 1.0f);
            d[k] = e ? dd : 0.0f;
            m[k] = e ? 1.0f : 0.0f;
        }

        __stcs(reinterpret_cast<float4*>(od), make_float4(d[0], d[1], d[2], d[3]));
        __stcs(reinterpret_cast<float4*>(om), make_float4(m[0], m[1], m[2], m[3]));
        od += NPTS;
        om += NPTS;
    }
}

extern "C" void kernel_launch(void* const* d_in, const int* in_sizes, int n_in,
                              void* d_out, int out_size) {
    const float* pos = (const float*)d_in[0];
    float* out = (float*)d_out;

    dim3 grid(NPTS / JTILE, NPTS / ITILE);  // (8, 128) = 1024 CTAs
    radius_kernel<<<grid, TPB>>>(pos, out);
}